// round 4
// baseline (speedup 1.0000x reference)
#include <cuda_runtime.h>

// B3-spline à-trous UWT, LEVEL=3.  x:(8,1024,1024) f32 -> (8,4,1024,1024) f32
// Per level j (d=2^j): c_{j+1} = (h x h)*c_j (reflect pad), w_{j+1} = c_j - c_{j+1}.
// Vertical pass: register-rolling window over dilation-strided row chains (no smem
// input tile, no barrier). Horizontal pass: smem exchange of vertical results.

#define IMG_H 1024
#define IMG_W 1024
#define NBATCH 8
#define PLANE (IMG_H * IMG_W)
#define W4 (IMG_W / 4)

__device__ float g_scratch1[NBATCH * PLANE];
__device__ float g_scratch2[NBATCH * PLANE];

__device__ __forceinline__ int reflect_i(int i, int n) {
    return i < 0 ? -i : (i >= n ? 2 * n - 2 - i : i);
}

template <int D, int LOGD>
__global__ __launch_bounds__(320, 5) void uwt_level_kernel(
    const float* __restrict__ cin,
    float* __restrict__ wout, long wbs,
    float* __restrict__ cout, long cbs)
{
    constexpr int TX = 64, TY = 64;
    constexpr int PADX = 8;                 // x halo (covers 2*D <= 8), f4 aligned
    constexpr int NC4  = 20;                // data f4 columns: TX/4 + 2*PADX/4
    constexpr int LW   = 84;                // smem pitch (floats), conflict-free
    constexpr int NJ   = 16;                // row-threads
    constexpr int G    = 4;                 // outputs per chain (NJ*G == TY)

    __shared__ __align__(16) float s1[TY][LW];   // vertical-conv results

    const int tid = threadIdx.x;            // 0..319
    const int b   = blockIdx.z;
    const int x0  = blockIdx.x * TX;
    const int y0  = blockIdx.y * TY;

    const float* in = cin + (long)b * PLANE;

    // ================= vertical pass (registers only) =================
    {
        const int c4 = tid % NC4;            // f4 column 0..19
        const int j  = tid / NC4;            // 0..15
        const int p  = j & (D - 1);          // phase within dilation
        const int k  = j >> LOGD;            // chain index
        const int tb = p + D * (k * G);      // first output row (tile-local)
        const int xl = x0 - PADX + c4 * 4;   // leftmost float of this f4
        const bool xint = (x0 >= PADX) && (x0 + TX + PADX <= IMG_W);

        float4 win[5];

        auto ldrow = [&](int m) -> float4 {
            int gy = reflect_i(y0 + tb + D * (m - 2), IMG_H);
            const float* rp = in + gy * IMG_W;
            if (xint) {
                return *(const float4*)(rp + xl);
            } else {
                float4 r;
                r.x = rp[reflect_i(xl + 0, IMG_W)];
                r.y = rp[reflect_i(xl + 1, IMG_W)];
                r.z = rp[reflect_i(xl + 2, IMG_W)];
                r.w = rp[reflect_i(xl + 3, IMG_W)];
                return r;
            }
        };

        win[0] = ldrow(0); win[1] = ldrow(1);
        win[2] = ldrow(2); win[3] = ldrow(3);

        #pragma unroll
        for (int g = 0; g < G; g++) {
            win[4] = ldrow(g + 4);
            float4 v;
            v.x = 0.0625f * (win[0].x + win[4].x) + 0.25f * (win[1].x + win[3].x) + 0.375f * win[2].x;
            v.y = 0.0625f * (win[0].y + win[4].y) + 0.25f * (win[1].y + win[3].y) + 0.375f * win[2].y;
            v.z = 0.0625f * (win[0].z + win[4].z) + 0.25f * (win[1].z + win[3].z) + 0.375f * win[2].z;
            v.w = 0.0625f * (win[0].w + win[4].w) + 0.25f * (win[1].w + win[3].w) + 0.375f * win[2].w;
            *(float4*)&s1[tb + D * g][c4 * 4] = v;
            win[0] = win[1]; win[1] = win[2]; win[2] = win[3]; win[3] = win[4];
        }
    }
    __syncthreads();

    // ================= horizontal pass + outputs =================
    {
        float* wo = wout + (long)b * wbs;
        float* co = cout + (long)b * cbs;

        for (int i = tid; i < TY * 16; i += 320) {
            const int r  = i >> 4;            // tile row 0..63
            const int oc = i & 15;            // output f4 column 0..15
            const float* row = s1[r];
            float4 v;
            if constexpr (D == 4) {
                // taps f4-aligned: offsets -8,-4,0,+4,+8 floats
                float4 A0 = *(const float4*)&row[(oc + 0) * 4];
                float4 A1 = *(const float4*)&row[(oc + 1) * 4];
                float4 A2 = *(const float4*)&row[(oc + 2) * 4];
                float4 A3 = *(const float4*)&row[(oc + 3) * 4];
                float4 A4 = *(const float4*)&row[(oc + 4) * 4];
                v.x = 0.0625f * (A0.x + A4.x) + 0.25f * (A1.x + A3.x) + 0.375f * A2.x;
                v.y = 0.0625f * (A0.y + A4.y) + 0.25f * (A1.y + A3.y) + 0.375f * A2.y;
                v.z = 0.0625f * (A0.z + A4.z) + 0.25f * (A1.z + A3.z) + 0.375f * A2.z;
                v.w = 0.0625f * (A0.w + A4.w) + 0.25f * (A1.w + A3.w) + 0.375f * A2.w;
            } else {
                // 12 contiguous floats [center-4, center+8)
                float4 B0 = *(const float4*)&row[(oc + 1) * 4];
                float4 B1 = *(const float4*)&row[(oc + 2) * 4];
                float4 B2 = *(const float4*)&row[(oc + 3) * 4];
                float f[12] = {B0.x, B0.y, B0.z, B0.w,
                               B1.x, B1.y, B1.z, B1.w,
                               B2.x, B2.y, B2.z, B2.w};
                v.x = 0.0625f * (f[4 - 2*D] + f[4 + 2*D]) + 0.25f * (f[4 - D] + f[4 + D]) + 0.375f * f[4];
                v.y = 0.0625f * (f[5 - 2*D] + f[5 + 2*D]) + 0.25f * (f[5 - D] + f[5 + D]) + 0.375f * f[5];
                v.z = 0.0625f * (f[6 - 2*D] + f[6 + 2*D]) + 0.25f * (f[6 - D] + f[6 + D]) + 0.375f * f[6];
                v.w = 0.0625f * (f[7 - 2*D] + f[7 + 2*D]) + 0.25f * (f[7 - D] + f[7 + D]) + 0.375f * f[7];
            }
            // original center values (interior read, coalesced)
            const long go = (long)(y0 + r) * W4 + (x0 >> 2) + oc;
            float4 cc = ((const float4*)in)[go];
            float4 w4 = make_float4(cc.x - v.x, cc.y - v.y, cc.z - v.z, cc.w - v.w);
            ((float4*)wo)[go - 0] = w4;   // note: wo/co are per-batch base pointers
            ((float4*)co)[go - 0] = v;
        }
    }
}

extern "C" void kernel_launch(void* const* d_in, const int* in_sizes, int n_in,
                              void* d_out, int out_size)
{
    (void)in_sizes; (void)n_in; (void)out_size;
    const float* x = (const float*)d_in[0];
    float* out = (float*)d_out;

    float *c1, *c2;
    cudaGetSymbolAddress((void**)&c1, g_scratch1);
    cudaGetSymbolAddress((void**)&c2, g_scratch2);

    dim3 block(320, 1, 1);
    dim3 grid(IMG_W / 64, IMG_H / 64, NBATCH);

    const long IN_BS  = (long)PLANE;
    const long OUT_BS = 4L * PLANE;

    uwt_level_kernel<1, 0><<<grid, block>>>(x,  out + 0L * PLANE, OUT_BS, c1, IN_BS);
    uwt_level_kernel<2, 1><<<grid, block>>>(c1, out + 1L * PLANE, OUT_BS, c2, IN_BS);
    uwt_level_kernel<4, 2><<<grid, block>>>(c2, out + 2L * PLANE, OUT_BS,
                                                out + 3L * PLANE, OUT_BS);
}

// round 5
// speedup vs baseline: 1.4227x; 1.4227x over previous
#include <cuda_runtime.h>

// B3-spline à-trous UWT, LEVEL=3.  x:(8,1024,1024) f32 -> (8,4,1024,1024) f32
// Per level j (d=2^j): c_{j+1} = (h x h)*c_j (reflect pad), w_{j+1} = c_j - c_{j+1}.
// Phase 1: horizontal 5-tap straight from gmem (overlap absorbed by L1) -> smem.
// Phase 2: vertical 5-tap from smem with 2-output chains; w & c_next written out.
// Single __syncthreads per block.

#define IMG_H 1024
#define IMG_W 1024
#define NBATCH 8
#define PLANE (IMG_H * IMG_W)
#define W4 (IMG_W / 4)

__device__ float g_scratch1[NBATCH * PLANE];
__device__ float g_scratch2[NBATCH * PLANE];

__device__ __forceinline__ int reflect_i(int i, int n) {
    return i < 0 ? -i : (i >= n ? 2 * n - 2 - i : i);
}

template <int D, int LOGD>
__global__ __launch_bounds__(256, 6) void uwt_level_kernel(
    const float* __restrict__ cin,
    float* __restrict__ wout, long wbs,
    float* __restrict__ cout, long cbs)
{
    constexpr int TX = 64, TY = 64;
    constexpr int SH = TY + 4 * D;          // h-conv rows needed (68, 72, 80)
    constexpr int PITCH = 68;               // floats; 68 mod 32 = 4 -> no bank repeats

    __shared__ __align__(16) float s1[SH][PITCH];

    const int tid = threadIdx.x;            // 0..255
    const int b   = blockIdx.z;
    const int x0  = blockIdx.x * TX;
    const int y0  = blockIdx.y * TY;

    const float* in = cin + (long)b * PLANE;
    const bool xint = (x0 >= 8) && (x0 + TX + 8 <= IMG_W);
    const int xb4 = x0 >> 2;                // tile's first f4 column

    // ============ phase 1: horizontal 5-tap, gmem -> smem ============
    for (int i = tid; i < SH * 16; i += 256) {
        const int rr = i >> 4;              // s1 row 0..SH-1
        const int oc = i & 15;              // f4 column in tile
        const int gy = reflect_i(y0 - 2 * D + rr, IMG_H);
        const float* rp = in + gy * IMG_W;
        float4 v;
        if (xint) {
            const float4* rp4 = (const float4*)rp;
            if constexpr (D == 4) {
                // taps f4-aligned at offsets -2..+2 f4
                float4 A0 = rp4[xb4 + oc - 2];
                float4 A1 = rp4[xb4 + oc - 1];
                float4 A2 = rp4[xb4 + oc    ];
                float4 A3 = rp4[xb4 + oc + 1];
                float4 A4 = rp4[xb4 + oc + 2];
                v.x = 0.0625f * (A0.x + A4.x) + 0.25f * (A1.x + A3.x) + 0.375f * A2.x;
                v.y = 0.0625f * (A0.y + A4.y) + 0.25f * (A1.y + A3.y) + 0.375f * A2.y;
                v.z = 0.0625f * (A0.z + A4.z) + 0.25f * (A1.z + A3.z) + 0.375f * A2.z;
                v.w = 0.0625f * (A0.w + A4.w) + 0.25f * (A1.w + A3.w) + 0.375f * A2.w;
            } else {
                // 12 contiguous floats [xl-4, xl+8)
                float4 B0 = rp4[xb4 + oc - 1];
                float4 B1 = rp4[xb4 + oc    ];
                float4 B2 = rp4[xb4 + oc + 1];
                float f[12] = {B0.x, B0.y, B0.z, B0.w,
                               B1.x, B1.y, B1.z, B1.w,
                               B2.x, B2.y, B2.z, B2.w};
                v.x = 0.0625f * (f[4 - 2*D] + f[4 + 2*D]) + 0.25f * (f[4 - D] + f[4 + D]) + 0.375f * f[4];
                v.y = 0.0625f * (f[5 - 2*D] + f[5 + 2*D]) + 0.25f * (f[5 - D] + f[5 + D]) + 0.375f * f[5];
                v.z = 0.0625f * (f[6 - 2*D] + f[6 + 2*D]) + 0.25f * (f[6 - D] + f[6 + D]) + 0.375f * f[6];
                v.w = 0.0625f * (f[7 - 2*D] + f[7 + 2*D]) + 0.25f * (f[7 - D] + f[7 + D]) + 0.375f * f[7];
            }
        } else {
            const int xl = x0 + oc * 4;
            float o[4];
            #pragma unroll
            for (int n = 0; n < 4; n++) {
                float a0 = rp[reflect_i(xl + n - 2 * D, IMG_W)];
                float a1 = rp[reflect_i(xl + n -     D, IMG_W)];
                float a2 = rp[reflect_i(xl + n,         IMG_W)];
                float a3 = rp[reflect_i(xl + n +     D, IMG_W)];
                float a4 = rp[reflect_i(xl + n + 2 * D, IMG_W)];
                o[n] = 0.0625f * (a0 + a4) + 0.25f * (a1 + a3) + 0.375f * a2;
            }
            v = make_float4(o[0], o[1], o[2], o[3]);
        }
        *(float4*)&s1[rr][oc * 4] = v;
    }
    __syncthreads();

    // ============ phase 2: vertical 5-tap from smem, chains of 2 ============
    // s1 row index = tile row + 2D; output row r uses s1 rows r .. r+4D step D.
    // Chain covers output rows tb, tb+D sharing 6 tap rows tb .. tb+5D (s1 coords).
    float* wo = wout + (long)b * wbs;
    float* co = cout + (long)b * cbs;

    #pragma unroll
    for (int t = 0; t < 2; t++) {
        const int cid = tid + t * 256;       // 0..511
        const int col = cid & 15;            // f4 column
        const int j   = cid >> 4;            // 0..31 row-chain id
        const int p   = j & (D - 1);
        const int k   = j >> LOGD;
        const int tb  = p + D * (2 * k);     // first output row of this chain

        float4 a[6];
        #pragma unroll
        for (int m = 0; m < 6; m++)
            a[m] = *(const float4*)&s1[tb + m * D][col * 4];

        #pragma unroll
        for (int g = 0; g < 2; g++) {
            float4 v;
            v.x = 0.0625f * (a[g].x + a[g+4].x) + 0.25f * (a[g+1].x + a[g+3].x) + 0.375f * a[g+2].x;
            v.y = 0.0625f * (a[g].y + a[g+4].y) + 0.25f * (a[g+1].y + a[g+3].y) + 0.375f * a[g+2].y;
            v.z = 0.0625f * (a[g].z + a[g+4].z) + 0.25f * (a[g+1].z + a[g+3].z) + 0.375f * a[g+2].z;
            v.w = 0.0625f * (a[g].w + a[g+4].w) + 0.25f * (a[g+1].w + a[g+3].w) + 0.375f * a[g+2].w;

            const int  gy = y0 + tb + g * D;
            const long go = (long)gy * W4 + xb4 + col;
            const float4 cc = ((const float4*)in)[go];   // L1-resident
            float4 w4 = make_float4(cc.x - v.x, cc.y - v.y, cc.z - v.z, cc.w - v.w);
            ((float4*)wo)[go] = w4;
            ((float4*)co)[go] = v;
        }
    }
}

extern "C" void kernel_launch(void* const* d_in, const int* in_sizes, int n_in,
                              void* d_out, int out_size)
{
    (void)in_sizes; (void)n_in; (void)out_size;
    const float* x = (const float*)d_in[0];
    float* out = (float*)d_out;

    float *c1, *c2;
    cudaGetSymbolAddress((void**)&c1, g_scratch1);
    cudaGetSymbolAddress((void**)&c2, g_scratch2);

    dim3 block(256, 1, 1);
    dim3 grid(IMG_W / 64, IMG_H / 64, NBATCH);

    const long IN_BS  = (long)PLANE;
    const long OUT_BS = 4L * PLANE;

    uwt_level_kernel<1, 0><<<grid, block>>>(x,  out + 0L * PLANE, OUT_BS, c1, IN_BS);
    uwt_level_kernel<2, 1><<<grid, block>>>(c1, out + 1L * PLANE, OUT_BS, c2, IN_BS);
    uwt_level_kernel<4, 2><<<grid, block>>>(c2, out + 2L * PLANE, OUT_BS,
                                                out + 3L * PLANE, OUT_BS);
}